// round 1
// baseline (speedup 1.0000x reference)
#include <cuda_runtime.h>
#include <cuda_bf16.h>

// ---------------------------------------------------------------------------
// MessagePassing: out[q, :] += w_e * (ref_feat[r_e, :] @ kernel[k_e, :, :])
// Strategy: counting-sort edges by kernel id (27 buckets, tile-padded), then
// one block per 128-edge tile (all same kernel): smem-cached kernel matrix,
// weighted row gather into smem, fp32 FMA GEMM, coalesced atomicAdd scatter.
// ref_feat (16.7MB) and out (16.7MB) are L2-resident -> gather/scatter cheap.
// ---------------------------------------------------------------------------

#define D      64        // D1 == D2 == 64
#define TILE   128       // edges per tile
#define MAXK   32        // >= K0 (27)
#define MAX_E  1703936   // >= E + K0*TILE

__device__ int g_hist[MAXK];
__device__ int g_cursor[MAXK];
__device__ int g_pstart[MAXK + 1];     // padded bucket start (edge units)
__device__ int g_count[MAXK];          // real bucket size
__device__ int g_tile_start[MAXK + 1]; // cumulative tile index
__device__ int g_total_tiles;
__device__ int g_sorted[MAX_E];        // edge ids, bucketed by kernel

// ---- pass 0: zero histogram -----------------------------------------------
__global__ void init_kernel() {
    if (threadIdx.x < MAXK) g_hist[threadIdx.x] = 0;
}

// ---- pass 1: histogram of e_kernel ----------------------------------------
__global__ void hist_kernel(const int* __restrict__ ek, int E) {
    __shared__ int sh[MAXK];
    if (threadIdx.x < MAXK) sh[threadIdx.x] = 0;
    __syncthreads();
    for (int i = blockIdx.x * blockDim.x + threadIdx.x; i < E;
         i += gridDim.x * blockDim.x)
        atomicAdd(&sh[ek[i]], 1);
    __syncthreads();
    if (threadIdx.x < MAXK) {
        int v = sh[threadIdx.x];
        if (v) atomicAdd(&g_hist[threadIdx.x], v);
    }
}

// ---- pass 2: tiny serial scan (27 items) ----------------------------------
__global__ void scan_kernel(int K0) {
    if (threadIdx.x == 0 && blockIdx.x == 0) {
        int p = 0, t = 0;
        for (int k = 0; k < K0; ++k) {
            g_pstart[k] = p;
            g_tile_start[k] = t;
            g_cursor[k] = p;
            int c = g_hist[k];
            g_count[k] = c;
            int nt = (c + TILE - 1) / TILE;
            p += nt * TILE;
            t += nt;
        }
        g_pstart[K0] = p;
        g_tile_start[K0] = t;
        g_total_tiles = t;
    }
}

// ---- pass 3: scatter edge ids into buckets (warp-aggregated atomics) ------
__global__ void scatter_kernel(const int* __restrict__ ek, int E) {
    int i = blockIdx.x * blockDim.x + threadIdx.x;
    if (i >= E) return;
    int k = ek[i];
    unsigned act  = __activemask();
    unsigned mask = __match_any_sync(act, k);
    int lane   = threadIdx.x & 31;
    int leader = __ffs(mask) - 1;
    int rank   = __popc(mask & ((1u << lane) - 1));
    int base = 0;
    if (lane == leader) base = atomicAdd(&g_cursor[k], __popc(mask));
    base = __shfl_sync(mask, base, leader);
    g_sorted[base + rank] = i;
}

// ---- pass 4: fused tile GEMM + scatter ------------------------------------
// block = 256 threads = 8 warps. warp w owns edges [16w, 16w+16).
// lane l owns output channels l and l+32.  fp32 FMA inner product over D=64.
__global__ __launch_bounds__(256) void mp_kernel(
    const float* __restrict__ kernelW,   // [K0, D, D]
    const float* __restrict__ ref,       // [N, D]
    const int*   __restrict__ e_ref,
    const int*   __restrict__ e_query,
    const float* __restrict__ e_weight,
    float*       __restrict__ out)       // [M, D]
{
    extern __shared__ float dsm[];
    float* s_ker = dsm;                                  // D*D floats (16KB)
    float (*s_ref)[D] = (float (*)[D])(dsm + D * D);     // TILE*D floats (32KB)
    int* s_q = (int*)(dsm + D * D + TILE * D);           // TILE ints

    __shared__ int s_meta[3];  // k, base, n

    int b = blockIdx.x;
    if (b >= g_total_tiles) return;

    int t = threadIdx.x;
    if (t == 0) {
        int kk = 0;
        while (b >= g_tile_start[kk + 1]) kk++;
        int local = b - g_tile_start[kk];
        s_meta[0] = kk;
        s_meta[1] = g_pstart[kk] + local * TILE;
        int n = g_count[kk] - local * TILE;
        s_meta[2] = n > TILE ? TILE : n;
    }
    __syncthreads();
    int k = s_meta[0], base = s_meta[1], n = s_meta[2];

    // load kernel matrix [D][D] (row d, col o), float4 copies
    {
        const float4* km4 = (const float4*)(kernelW + (size_t)k * D * D);
        float4* sk4 = (float4*)s_ker;
        #pragma unroll
        for (int i = t; i < D * D / 4; i += 256) sk4[i] = km4[i];
    }

    // gather weighted ref rows: 2 threads per edge, 8 float4 each
    {
        int el = t >> 1, half = t & 1;
        if (el < n) {
            int e = g_sorted[base + el];
            int r = e_ref[e];
            float w = e_weight[e];
            const float4* src = (const float4*)(ref + (size_t)r * D) + half * 8;
            float4* dst = (float4*)(&s_ref[el][0]) + half * 8;
            #pragma unroll
            for (int j = 0; j < 8; ++j) {
                float4 v = src[j];
                v.x *= w; v.y *= w; v.z *= w; v.w *= w;
                dst[j] = v;
            }
        } else {
            float4 z = make_float4(0.f, 0.f, 0.f, 0.f);
            float4* dst = (float4*)(&s_ref[el][0]) + half * 8;
            #pragma unroll
            for (int j = 0; j < 8; ++j) dst[j] = z;
        }
        if (t < TILE) s_q[t] = (t < n) ? e_query[g_sorted[base + t]] : -1;
    }
    __syncthreads();

    int warp = t >> 5, lane = t & 31;
    int eb = warp * 16;

    float acc0[16], acc1[16];
    #pragma unroll
    for (int e = 0; e < 16; ++e) { acc0[e] = 0.f; acc1[e] = 0.f; }

    #pragma unroll 4
    for (int d = 0; d < D; d += 2) {
        float k00 = s_ker[d * D + lane];
        float k01 = s_ker[d * D + lane + 32];
        float k10 = s_ker[(d + 1) * D + lane];
        float k11 = s_ker[(d + 1) * D + lane + 32];
        #pragma unroll
        for (int e = 0; e < 16; ++e) {
            float2 a = *(const float2*)&s_ref[eb + e][d];  // warp-broadcast
            acc0[e] += a.x * k00 + a.y * k10;
            acc1[e] += a.x * k01 + a.y * k11;
        }
    }

    #pragma unroll
    for (int e = 0; e < 16; ++e) {
        int q = s_q[eb + e];
        if (q >= 0) {
            atomicAdd(&out[(size_t)q * D + lane],      acc0[e]);
            atomicAdd(&out[(size_t)q * D + lane + 32], acc1[e]);
        }
    }
}

// ---------------------------------------------------------------------------
extern "C" void kernel_launch(void* const* d_in, const int* in_sizes, int n_in,
                              void* d_out, int out_size) {
    const float* kernelW  = (const float*)d_in[0];
    const float* ref      = (const float*)d_in[1];
    const int*   e_kernel = (const int*)d_in[2];
    const int*   e_ref    = (const int*)d_in[3];
    const int*   e_query  = (const int*)d_in[4];
    // d_in[5] may be the scalar num_queries; weight is the last fp32 array.
    const float* e_weight =
        (n_in >= 7) ? (const float*)d_in[6] : (const float*)d_in[5];

    int E  = in_sizes[2];
    int K0 = in_sizes[0] / (D * D);

    cudaMemsetAsync(d_out, 0, (size_t)out_size * sizeof(float), 0);

    init_kernel<<<1, 32>>>();
    hist_kernel<<<256, 256>>>(e_kernel, E);
    scan_kernel<<<1, 1>>>(K0);
    scatter_kernel<<<(E + 255) / 256, 256>>>(e_kernel, E);

    int smem_bytes = (D * D + TILE * D) * sizeof(float) + TILE * sizeof(int);
    cudaFuncSetAttribute(mp_kernel, cudaFuncAttributeMaxDynamicSharedMemorySize,
                         smem_bytes);
    int max_tiles = (E + TILE - 1) / TILE + K0;
    mp_kernel<<<max_tiles, 256, smem_bytes>>>(kernelW, ref, e_ref, e_query,
                                              e_weight, (float*)d_out);
}

// round 3
// speedup vs baseline: 2.2259x; 2.2259x over previous
#include <cuda_runtime.h>
#include <cuda_bf16.h>
#include <cstdint>

// ---------------------------------------------------------------------------
// MessagePassing: out[q,:] += w_e * (ref[r_e,:] @ kernel[k_e,:,:])
// sm_103 (non-'a' target): tcgen05 unavailable -> use mma.sync tf32 (sm_80 ISA).
// 1) counting-sort edges by kernel id (block-aggregated atomics)
// 2) persistent blocks, one 128-edge same-kernel tile at a time:
//    gather rows -> SMEM tf32 (stride 68, conflict-free A-frag reads),
//    kernel matrix -> SMEM tf32 (stride 72, conflict-free B-frag reads,
//    native [d][o] layout, loaded only on k-change),
//    8 warps x 64 mma.m16n8k8.tf32, fp32 epilogue scale by w_e,
//    stride-65 restage -> coalesced atomicAdd scatter.
// ---------------------------------------------------------------------------

#define D      64
#define TILE   128
#define MAXK   32
#define MAX_E  1703936

__device__ int g_hist[MAXK];
__device__ int g_cursor[MAXK];
__device__ int g_pstart[MAXK + 1];
__device__ int g_count[MAXK];
__device__ int g_tile_start[MAXK + 1];
__device__ int g_total_tiles;
__device__ int g_sorted[MAX_E];

// ---- SMEM layout (byte offsets into dynamic smem) -------------------------
// A: 128 rows x stride 68 words = 34816 B (epilogue restage stride-65 reuses it)
// B: 64 rows x stride 72 words  = 18432 B
#define SA_STRIDE 68
#define SB_STRIDE 72
#define OFF_A     0u
#define OFF_B     34816u
#define OFF_Q     53248u
#define OFF_W     53760u
#define OFF_META  54272u
#define OFF_TS    54336u   // 33 ints
#define OFF_PS    54480u   // 33 ints
#define OFF_CN    54624u   // 32 ints
#define DYN_SMEM  55296

__device__ __forceinline__ uint32_t f2tf(float x) {
    uint32_t r;
    asm("cvt.rna.tf32.f32 %0, %1;" : "=r"(r) : "f"(x));
    return r;
}

__device__ __forceinline__ void mma_tf32(float& c0, float& c1, float& c2, float& c3,
                                         uint32_t a0, uint32_t a1, uint32_t a2,
                                         uint32_t a3, uint32_t b0, uint32_t b1) {
    asm volatile(
        "mma.sync.aligned.m16n8k8.row.col.f32.tf32.tf32.f32 "
        "{%0,%1,%2,%3}, {%4,%5,%6,%7}, {%8,%9}, {%0,%1,%2,%3};"
        : "+f"(c0), "+f"(c1), "+f"(c2), "+f"(c3)
        : "r"(a0), "r"(a1), "r"(a2), "r"(a3), "r"(b0), "r"(b1));
}

// ---- sort passes ----------------------------------------------------------
__global__ void init_kernel() {
    if (threadIdx.x < MAXK) g_hist[threadIdx.x] = 0;
}

__global__ void hist_kernel(const int* __restrict__ ek, int E) {
    __shared__ int sh[MAXK];
    if (threadIdx.x < MAXK) sh[threadIdx.x] = 0;
    __syncthreads();
    for (int i = blockIdx.x * blockDim.x + threadIdx.x; i < E;
         i += gridDim.x * blockDim.x)
        atomicAdd(&sh[ek[i]], 1);
    __syncthreads();
    if (threadIdx.x < MAXK) {
        int v = sh[threadIdx.x];
        if (v) atomicAdd(&g_hist[threadIdx.x], v);
    }
}

__global__ void scan_kernel(int K0) {
    if (threadIdx.x == 0 && blockIdx.x == 0) {
        int p = 0, t = 0;
        for (int k = 0; k < K0; ++k) {
            g_pstart[k] = p;
            g_tile_start[k] = t;
            g_cursor[k] = p;
            int c = g_hist[k];
            g_count[k] = c;
            int nt = (c + TILE - 1) / TILE;
            p += nt * TILE;
            t += nt;
        }
        g_pstart[K0] = p;
        g_tile_start[K0] = t;
        g_total_tiles = t;
        for (int k = K0; k < MAXK; ++k) g_tile_start[k + 1] = t;
    }
}

// block-aggregated scatter: one global atomic per (block, k)
__global__ void scatter_kernel(const int* __restrict__ ek, int E) {
    __shared__ int sc[MAXK], sb[MAXK];
    int chunk = (E + gridDim.x - 1) / gridDim.x;
    int lo = blockIdx.x * chunk;
    int hi = min(lo + chunk, E);
    if (threadIdx.x < MAXK) sc[threadIdx.x] = 0;
    __syncthreads();
    for (int i = lo + threadIdx.x; i < hi; i += blockDim.x)
        atomicAdd(&sc[ek[i]], 1);
    __syncthreads();
    if (threadIdx.x < MAXK) {
        int c = sc[threadIdx.x];
        sb[threadIdx.x] = c ? atomicAdd(&g_cursor[threadIdx.x], c) : 0;
        sc[threadIdx.x] = 0;
    }
    __syncthreads();
    for (int i = lo + threadIdx.x; i < hi; i += blockDim.x) {
        int k = ek[i];
        int pos = sb[k] + atomicAdd(&sc[k], 1);
        g_sorted[pos] = i;
    }
}

// ---- main fused MMA kernel ------------------------------------------------
__global__ __launch_bounds__(256) void mp_mma(
    const float* __restrict__ kernelW,   // [K0, D, D]
    const float* __restrict__ ref,       // [N, D]
    const int*   __restrict__ e_ref,
    const int*   __restrict__ e_query,
    const float* __restrict__ e_weight,
    float*       __restrict__ out)
{
    extern __shared__ char sm[];
    uint32_t* s_A  = (uint32_t*)(sm + OFF_A);   // tf32 bits, stride SA_STRIDE
    uint32_t* s_B  = (uint32_t*)(sm + OFF_B);   // tf32 bits, stride SB_STRIDE
    int*      s_q  = (int*)(sm + OFF_Q);
    float*    s_w  = (float*)(sm + OFF_W);
    int*      s_meta = (int*)(sm + OFF_META);
    int*      s_ts = (int*)(sm + OFF_TS);
    int*      s_ps = (int*)(sm + OFF_PS);
    int*      s_cn = (int*)(sm + OFF_CN);

    int tid = threadIdx.x, wid = tid >> 5, lane = tid & 31;
    int g = lane >> 2, t4 = lane & 3;

    if (tid < MAXK + 1) s_ts[tid] = g_tile_start[tid];
    else if (tid >= 64 && tid < 64 + MAXK + 1) s_ps[tid - 64] = g_pstart[tid - 64];
    else if (tid >= 128 && tid < 128 + MAXK) s_cn[tid - 128] = g_count[tid - 128];
    __syncthreads();

    int total = g_total_tiles;
    int per = (total + gridDim.x - 1) / gridDim.x;
    int t0 = blockIdx.x * per;
    int t1 = min(t0 + per, total);
    int prevk = -1;

    for (int tile = t0; tile < t1; ++tile) {
        if (tid == 0) {
            int kk = 0;
            while (tile >= s_ts[kk + 1]) kk++;
            int local = tile - s_ts[kk];
            s_meta[0] = kk;
            s_meta[1] = s_ps[kk] + local * TILE;
            int n = s_cn[kk] - local * TILE;
            s_meta[2] = n > TILE ? TILE : n;
        }
        __syncthreads();
        int k = s_meta[0], ebase = s_meta[1], n = s_meta[2];

        // ---- gather A: 2 threads/row, tf32-convert, stride-68 -------------
        {
            int row = tid >> 1, half = tid & 1;
            uint32_t* dst = s_A + row * SA_STRIDE + half * 32;
            if (row < n) {
                int e = g_sorted[ebase + row];
                int r = e_ref[e];
                if (half == 0) {
                    s_q[row] = e_query[e];
                    s_w[row] = e_weight[e];
                }
                const float4* src = (const float4*)(ref + (size_t)r * D) + half * 8;
                #pragma unroll
                for (int j = 0; j < 8; ++j) {
                    float4 v = src[j];
                    uint4 u;
                    u.x = f2tf(v.x); u.y = f2tf(v.y);
                    u.z = f2tf(v.z); u.w = f2tf(v.w);
                    *(uint4*)(dst + j * 4) = u;
                }
            } else {
                if (half == 0) { s_q[row] = -1; s_w[row] = 0.f; }
                uint4 z = make_uint4(0u, 0u, 0u, 0u);
                #pragma unroll
                for (int j = 0; j < 8; ++j) *(uint4*)(dst + j * 4) = z;
            }
        }

        // ---- load B on k-change: native [d][o], tf32, stride-72 -----------
        if (k != prevk) {
            const float* kw = kernelW + (size_t)k * D * D;
            #pragma unroll
            for (int i = 0; i < 4; ++i) {
                int lin = tid + i * 256;          // lin = d*16 + o4
                int d = lin >> 4, o4 = lin & 15;
                float4 v = *(const float4*)(kw + d * D + o4 * 4);
                uint4 u;
                u.x = f2tf(v.x); u.y = f2tf(v.y);
                u.z = f2tf(v.z); u.w = f2tf(v.w);
                *(uint4*)(s_B + d * SB_STRIDE + o4 * 4) = u;
            }
            prevk = k;
        }
        __syncthreads();

        // ---- 8 warps x mma.m16n8k8.tf32: warp owns rows [16w,16w+16) ------
        float acc[8][4];
        #pragma unroll
        for (int i = 0; i < 8; ++i)
            #pragma unroll
            for (int j = 0; j < 4; ++j) acc[i][j] = 0.f;

        {
            const uint32_t* A0 = s_A + (wid * 16 + g) * SA_STRIDE;
            const uint32_t* A1 = A0 + 8 * SA_STRIDE;
            #pragma unroll
            for (int k0 = 0; k0 < D; k0 += 8) {
                uint32_t a0 = A0[k0 + t4];
                uint32_t a1 = A1[k0 + t4];
                uint32_t a2 = A0[k0 + t4 + 4];
                uint32_t a3 = A1[k0 + t4 + 4];
                const uint32_t* B0 = s_B + (k0 + t4) * SB_STRIDE + g;
                const uint32_t* B1 = B0 + 4 * SB_STRIDE;
                #pragma unroll
                for (int n0 = 0; n0 < 8; ++n0) {
                    uint32_t b0 = B0[n0 * 8];
                    uint32_t b1 = B1[n0 * 8];
                    mma_tf32(acc[n0][0], acc[n0][1], acc[n0][2], acc[n0][3],
                             a0, a1, a2, a3, b0, b1);
                }
            }
        }
        __syncthreads();   // done reading s_A; reuse as restage buffer

        // ---- epilogue: fp32 weight scale, stride-65 restage ---------------
        {
            float* so = (float*)s_A;
            int row0 = wid * 16 + g, row1 = row0 + 8;
            float w0 = s_w[row0], w1 = s_w[row1];
            #pragma unroll
            for (int n0 = 0; n0 < 8; ++n0) {
                int col = n0 * 8 + t4 * 2;
                so[row0 * 65 + col]     = acc[n0][0] * w0;
                so[row0 * 65 + col + 1] = acc[n0][1] * w0;
                so[row1 * 65 + col]     = acc[n0][2] * w1;
                so[row1 * 65 + col + 1] = acc[n0][3] * w1;
            }
        }
        __syncthreads();

        // ---- coalesced scatter: warp covers one row's 32+32 channels ------
        {
            const float* so = (const float*)s_A;
            for (int e = wid; e < TILE; e += 8) {
                int q = s_q[e];
                if (q >= 0) {
                    atomicAdd(&out[(size_t)q * D + lane],      so[e * 65 + lane]);
                    atomicAdd(&out[(size_t)q * D + 32 + lane], so[e * 65 + 32 + lane]);
                }
            }
        }
        __syncthreads();   // protect s_A/s_q/s_w/s_meta before next tile
    }
}

// ---------------------------------------------------------------------------
extern "C" void kernel_launch(void* const* d_in, const int* in_sizes, int n_in,
                              void* d_out, int out_size) {
    const float* kernelW  = (const float*)d_in[0];
    const float* ref      = (const float*)d_in[1];
    const int*   e_kernel = (const int*)d_in[2];
    const int*   e_ref    = (const int*)d_in[3];
    const int*   e_query  = (const int*)d_in[4];
    const float* e_weight =
        (n_in >= 7) ? (const float*)d_in[6] : (const float*)d_in[5];

    int E  = in_sizes[2];
    int K0 = in_sizes[0] / (D * D);

    cudaMemsetAsync(d_out, 0, (size_t)out_size * sizeof(float), 0);

    init_kernel<<<1, 32>>>();
    hist_kernel<<<256, 256>>>(e_kernel, E);
    scan_kernel<<<1, 1>>>(K0);
    scatter_kernel<<<592, 256>>>(e_kernel, E);

    cudaFuncSetAttribute(mp_mma, cudaFuncAttributeMaxDynamicSharedMemorySize,
                         DYN_SMEM);
    mp_mma<<<592, 256, DYN_SMEM>>>(kernelW, ref, e_ref, e_query, e_weight,
                                   (float*)d_out);
}

// round 4
// speedup vs baseline: 2.8454x; 1.2783x over previous
#include <cuda_runtime.h>
#include <cuda_bf16.h>
#include <cstdint>

// ---------------------------------------------------------------------------
// MessagePassing: out[q,:] += w_e * (ref[r_e,:] @ kernel[k_e,:,:])
// R4: cp.async double-buffered gather pipeline + fragment-major B smem
// (4x LDS.128 per warp per k-step) + direct red.global.add.v2.f32 epilogue.
// ---------------------------------------------------------------------------

#define D      64
#define TILE   128
#define MAXK   32
#define MAX_E  1703936
#define GRID   296
#define MAXT   64         // max tiles per block (<=42 actual)

__device__ int g_hist[MAXK];
__device__ int g_cursor[MAXK];
__device__ int g_pstart[MAXK + 1];
__device__ int g_count[MAXK];
__device__ int g_tile_start[MAXK + 1];
__device__ int g_total_tiles;
__device__ int g_sorted[MAX_E];

// ---- SMEM layout (byte offsets) -------------------------------------------
#define SA_STRIDE 68                       // words per A row (conflict-free)
#define SA_BYTES  (TILE * SA_STRIDE * 4)   // 34816 per buffer
#define OFF_A0    0u
#define OFF_A1    34816u
#define OFF_B     69632u                   // 8 steps x 32 lanes x 20 words
#define OFF_Q     90112u                   // 2 x 128 ints
#define OFF_W     91136u                   // 2 x 128 floats
#define OFF_MK    92160u                   // MAXT ints
#define OFF_MB    92416u
#define OFF_MN    92672u
#define OFF_TS    92928u                   // 33 ints
#define OFF_PS    93072u
#define OFF_CN    93216u
#define DYN_SMEM  93440

__device__ __forceinline__ uint32_t smem_u32(const void* p) {
    uint32_t a;
    asm("{ .reg .u64 t; cvta.to.shared.u64 t, %1; cvt.u32.u64 %0, t; }"
        : "=r"(a) : "l"(p));
    return a;
}
__device__ __forceinline__ uint32_t f2tf(float x) {
    uint32_t r;
    asm("cvt.rna.tf32.f32 %0, %1;" : "=r"(r) : "f"(x));
    return r;
}
__device__ __forceinline__ void cp16(uint32_t dst, const void* src, int sz) {
    asm volatile("cp.async.cg.shared.global [%0], [%1], 16, %2;"
                 :: "r"(dst), "l"(src), "r"(sz) : "memory");
}
#define CP_COMMIT() asm volatile("cp.async.commit_group;" ::: "memory")
#define CP_WAIT0()  asm volatile("cp.async.wait_group 0;" ::: "memory")

__device__ __forceinline__ void red_v2(float* p, float a, float b) {
    asm volatile("red.global.add.v2.f32 [%0], {%1, %2};"
                 :: "l"(p), "f"(a), "f"(b) : "memory");
}

__device__ __forceinline__ void mma_tf32(float& c0, float& c1, float& c2, float& c3,
                                         uint32_t a0, uint32_t a1, uint32_t a2,
                                         uint32_t a3, uint32_t b0, uint32_t b1) {
    asm volatile(
        "mma.sync.aligned.m16n8k8.row.col.f32.tf32.tf32.f32 "
        "{%0,%1,%2,%3}, {%4,%5,%6,%7}, {%8,%9}, {%0,%1,%2,%3};"
        : "+f"(c0), "+f"(c1), "+f"(c2), "+f"(c3)
        : "r"(a0), "r"(a1), "r"(a2), "r"(a3), "r"(b0), "r"(b1));
}

// ---- sort passes ----------------------------------------------------------
__global__ void init_kernel() {
    if (threadIdx.x < MAXK) g_hist[threadIdx.x] = 0;
}

__global__ void hist_kernel(const int* __restrict__ ek, int E) {
    __shared__ int sh[MAXK];
    if (threadIdx.x < MAXK) sh[threadIdx.x] = 0;
    __syncthreads();
    for (int i = blockIdx.x * blockDim.x + threadIdx.x; i < E;
         i += gridDim.x * blockDim.x)
        atomicAdd(&sh[ek[i]], 1);
    __syncthreads();
    if (threadIdx.x < MAXK) {
        int v = sh[threadIdx.x];
        if (v) atomicAdd(&g_hist[threadIdx.x], v);
    }
}

__global__ void scan_kernel(int K0) {
    if (threadIdx.x == 0 && blockIdx.x == 0) {
        int p = 0, t = 0;
        for (int k = 0; k < K0; ++k) {
            g_pstart[k] = p;
            g_tile_start[k] = t;
            g_cursor[k] = p;
            int c = g_hist[k];
            g_count[k] = c;
            int nt = (c + TILE - 1) / TILE;
            p += nt * TILE;
            t += nt;
        }
        g_pstart[K0] = p;
        g_tile_start[K0] = t;
        g_total_tiles = t;
        for (int k = K0; k < MAXK; ++k) g_tile_start[k + 1] = t;
    }
}

__global__ void scatter_kernel(const int* __restrict__ ek, int E) {
    __shared__ int sc[MAXK], sb[MAXK];
    int chunk = (E + gridDim.x - 1) / gridDim.x;
    int lo = blockIdx.x * chunk;
    int hi = min(lo + chunk, E);
    if (threadIdx.x < MAXK) sc[threadIdx.x] = 0;
    __syncthreads();
    for (int i = lo + threadIdx.x; i < hi; i += blockDim.x)
        atomicAdd(&sc[ek[i]], 1);
    __syncthreads();
    if (threadIdx.x < MAXK) {
        int c = sc[threadIdx.x];
        sb[threadIdx.x] = c ? atomicAdd(&g_cursor[threadIdx.x], c) : 0;
        sc[threadIdx.x] = 0;
    }
    __syncthreads();
    for (int i = lo + threadIdx.x; i < hi; i += blockDim.x) {
        int k = ek[i];
        int pos = sb[k] + atomicAdd(&sc[k], 1);
        g_sorted[pos] = i;
    }
}

// ---- main fused MMA kernel ------------------------------------------------
__global__ __launch_bounds__(256) void mp_mma(
    const float* __restrict__ kernelW,
    const float* __restrict__ ref,
    const int*   __restrict__ e_ref,
    const int*   __restrict__ e_query,
    const float* __restrict__ e_weight,
    float*       __restrict__ out)
{
    extern __shared__ char sm[];
    uint32_t sa0 = smem_u32(sm + OFF_A0);
    uint32_t sa1 = smem_u32(sm + OFF_A1);
    uint32_t*   s_Bw = (uint32_t*)(sm + OFF_B);
    const uint4* s_B4 = (const uint4*)(sm + OFF_B);
    int   (*s_q)[TILE] = (int (*)[TILE])(sm + OFF_Q);
    float (*s_w)[TILE] = (float (*)[TILE])(sm + OFF_W);
    int* s_mk = (int*)(sm + OFF_MK);
    int* s_mb = (int*)(sm + OFF_MB);
    int* s_mn = (int*)(sm + OFF_MN);
    int* s_ts = (int*)(sm + OFF_TS);
    int* s_ps = (int*)(sm + OFF_PS);
    int* s_cn = (int*)(sm + OFF_CN);

    int tid = threadIdx.x, wid = tid >> 5, lane = tid & 31;
    int g = lane >> 2, t4 = lane & 3;

    if (tid < MAXK + 1) s_ts[tid] = g_tile_start[tid];
    else if (tid >= 64 && tid < 64 + MAXK + 1) s_ps[tid - 64] = g_pstart[tid - 64];
    else if (tid >= 128 && tid < 128 + MAXK) s_cn[tid - 128] = g_count[tid - 128];
    __syncthreads();

    int total = g_total_tiles;
    int per = (total + GRID - 1) / GRID;
    int t0 = blockIdx.x * per;
    int t1 = min(t0 + per, total);
    int ntiles = t1 - t0;
    if (ntiles <= 0) return;

    // precompute per-tile meta (k, edge base, valid count)
    for (int j = tid; j < ntiles; j += 256) {
        int tile = t0 + j;
        int kk = 0;
        while (tile >= s_ts[kk + 1]) kk++;
        int local = tile - s_ts[kk];
        s_mk[j] = kk;
        s_mb[j] = s_ps[kk] + local * TILE;
        int n = s_cn[kk] - local * TILE;
        s_mn[j] = n > TILE ? TILE : n;
    }
    __syncthreads();

    int row  = tid >> 1, half = tid & 1;
    uint32_t dst_off = (uint32_t)row * (SA_STRIDE * 4) + (uint32_t)half * 128u;

    // ---- prologue: gather tile 0 into buf0 --------------------------------
    {
        int n0 = s_mn[0], base = s_mb[0];
        int r = -1, q = -1;
        float w = 0.f;
        if (row < n0) {
            int e = g_sorted[base + row];
            r = e_ref[e];
            q = e_query[e];
            w = e_weight[e];
        }
        if (half == 0) { s_q[0][row] = q; s_w[0][row] = w; }
        const char* src = (const char*)(ref + (size_t)(r < 0 ? 0 : r) * D) + half * 128;
        int sz = (r < 0) ? 0 : 16;
        uint32_t d0 = sa0 + dst_off;
        #pragma unroll
        for (int j = 0; j < 8; ++j) cp16(d0 + j * 16, src + j * 16, sz);
        CP_COMMIT();
    }

    // prefetch indices for tile 1
    int r_nx = -1, q_nx = -1;
    float w_nx = 0.f;
    if (ntiles > 1) {
        int n1 = s_mn[1], base = s_mb[1];
        if (row < n1) {
            int e = g_sorted[base + row];
            r_nx = e_ref[e];
            q_nx = e_query[e];
            w_nx = e_weight[e];
        }
    }

    int prevk = -1;
    for (int ii = 0; ii < ntiles; ++ii) {
        int buf = ii & 1;
        uint32_t sa = buf ? sa1 : sa0;
        uint32_t sb = buf ? sa0 : sa1;
        int k = s_mk[ii];

        CP_WAIT0();
        __syncthreads();

        // rebuild fragment-major B on kernel change (block-uniform branch)
        if (k != prevk) {
            const float* kw = kernelW + (size_t)k * D * D;
            int s = tid >> 5, l2 = tid & 31;
            int g2 = l2 >> 2, t42 = l2 & 3;
            uint32_t* bp = s_Bw + (s * 32 + l2) * 20;
            const float* row0 = kw + (8 * s + t42) * D + g2;
            const float* row1 = row0 + 4 * D;
            #pragma unroll
            for (int n = 0; n < 8; ++n) {
                bp[2 * n]     = f2tf(row0[8 * n]);
                bp[2 * n + 1] = f2tf(row1[8 * n]);
            }
            prevk = k;
            __syncthreads();
        }

        // issue gather for tile ii+1 into the other buffer
        if (ii + 1 < ntiles) {
            if (half == 0) { s_q[buf ^ 1][row] = q_nx; s_w[buf ^ 1][row] = w_nx; }
            const char* src =
                (const char*)(ref + (size_t)(r_nx < 0 ? 0 : r_nx) * D) + half * 128;
            int sz = (r_nx < 0) ? 0 : 16;
            uint32_t d1 = sb + dst_off;
            #pragma unroll
            for (int j = 0; j < 8; ++j) cp16(d1 + j * 16, src + j * 16, sz);
        }
        CP_COMMIT();

        // prefetch indices for tile ii+2
        r_nx = -1; q_nx = -1; w_nx = 0.f;
        if (ii + 2 < ntiles) {
            int nn = s_mn[ii + 2], base = s_mb[ii + 2];
            if (row < nn) {
                int e = g_sorted[base + row];
                r_nx = e_ref[e];
                q_nx = e_query[e];
                w_nx = e_weight[e];
            }
        }

        // ---- MMA: warp owns rows [16w, 16w+16) ----------------------------
        float acc[8][4];
        #pragma unroll
        for (int i = 0; i < 8; ++i)
            #pragma unroll
            for (int j = 0; j < 4; ++j) acc[i][j] = 0.f;

        {
            const uint32_t* A =
                (const uint32_t*)(sm + (buf ? OFF_A1 : OFF_A0));
            const uint32_t* A0 = A + (wid * 16 + g) * SA_STRIDE;
            const uint32_t* A1 = A0 + 8 * SA_STRIDE;
            #pragma unroll
            for (int s = 0; s < 8; ++s) {
                int k0 = s * 8;
                uint32_t a0 = A0[k0 + t4];
                uint32_t a1 = A1[k0 + t4];
                uint32_t a2 = A0[k0 + t4 + 4];
                uint32_t a3 = A1[k0 + t4 + 4];
                const uint4* bp = s_B4 + (s * 160 + lane * 5);
                #pragma unroll
                for (int m = 0; m < 4; ++m) {
                    uint4 bb = bp[m];
                    mma_tf32(acc[2 * m][0], acc[2 * m][1], acc[2 * m][2],
                             acc[2 * m][3], a0, a1, a2, a3, bb.x, bb.y);
                    mma_tf32(acc[2 * m + 1][0], acc[2 * m + 1][1],
                             acc[2 * m + 1][2], acc[2 * m + 1][3],
                             a0, a1, a2, a3, bb.z, bb.w);
                }
            }
        }

        // ---- epilogue: weight-scale + direct vector atomics ---------------
        {
            int r0 = wid * 16 + g, r1 = r0 + 8;
            int q0 = s_q[buf][r0], q1 = s_q[buf][r1];
            float w0 = s_w[buf][r0], w1 = s_w[buf][r1];
            if (q0 >= 0) {
                float* p0 = out + (size_t)q0 * D + t4 * 2;
                #pragma unroll
                for (int n = 0; n < 8; ++n)
                    red_v2(p0 + n * 8, acc[n][0] * w0, acc[n][1] * w0);
            }
            if (q1 >= 0) {
                float* p1 = out + (size_t)q1 * D + t4 * 2;
                #pragma unroll
                for (int n = 0; n < 8; ++n)
                    red_v2(p1 + n * 8, acc[n][2] * w1, acc[n][3] * w1);
            }
        }
    }
}

// ---------------------------------------------------------------------------
extern "C" void kernel_launch(void* const* d_in, const int* in_sizes, int n_in,
                              void* d_out, int out_size) {
    const float* kernelW  = (const float*)d_in[0];
    const float* ref      = (const float*)d_in[1];
    const int*   e_kernel = (const int*)d_in[2];
    const int*   e_ref    = (const int*)d_in[3];
    const int*   e_query  = (const int*)d_in[4];
    const float* e_weight =
        (n_in >= 7) ? (const float*)d_in[6] : (const float*)d_in[5];

    int E  = in_sizes[2];
    int K0 = in_sizes[0] / (D * D);

    cudaMemsetAsync(d_out, 0, (size_t)out_size * sizeof(float), 0);

    init_kernel<<<1, 32>>>();
    hist_kernel<<<256, 256>>>(e_kernel, E);
    scan_kernel<<<1, 1>>>(K0);
    scatter_kernel<<<592, 256>>>(e_kernel, E);

    cudaFuncSetAttribute(mp_mma, cudaFuncAttributeMaxDynamicSharedMemorySize,
                         DYN_SMEM);
    mp_mma<<<GRID, 256, DYN_SMEM>>>(kernelW, ref, e_ref, e_query, e_weight,
                                    (float*)d_out);
}

// round 5
// speedup vs baseline: 3.8242x; 1.3440x over previous
#include <cuda_runtime.h>
#include <cuda_fp16.h>
#include <cstdint>

// ---------------------------------------------------------------------------
// MessagePassing: out[q,:] += w_e * (ref[r_e,:] @ kernel[k_e,:,:])
// R5: fp16 mma.sync m16n8k16 (same 10-bit mantissa as tf32, 2x rate),
// global fp16 mirror of ref_feat (halves gather bytes, no in-tile convert),
// cp.async double-buffered pipeline + fragment-major B + red.global.add.v2.
// ---------------------------------------------------------------------------

#define D      64
#define TILE   128
#define MAXK   32
#define MAX_E  1703936
#define MAX_N  65536
#define GRID   296
#define MAXT   64

__device__ int g_hist[MAXK];
__device__ int g_cursor[MAXK];
__device__ int g_pstart[MAXK + 1];
__device__ int g_count[MAXK];
__device__ int g_tile_start[MAXK + 1];
__device__ int g_total_tiles;
__device__ int g_sorted[MAX_E];
__device__ uint32_t g_ref16[MAX_N * 32];   // fp16x2 mirror of ref_feat

// ---- SMEM layout ----------------------------------------------------------
// A16: 128 rows x 36 words (144B) per buffer -> frag LDS bank = 4g+t4 (clean)
#define SA_WORDS  36
#define SA_BYTES  (TILE * SA_WORDS * 4)    // 18432
#define OFF_A0    0u
#define OFF_A1    18432u
#define OFF_B     36864u                   // 4 steps x 32 lanes x 20 words = 10240
#define OFF_Q     47104u                   // 2 x 128 ints
#define OFF_W     48128u                   // 2 x 128 floats
#define OFF_MK    49152u
#define OFF_MB    49408u
#define OFF_MN    49664u
#define OFF_TS    49920u                   // 33 ints
#define OFF_PS    50064u
#define OFF_CN    50208u
#define DYN_SMEM  50432

__device__ __forceinline__ uint32_t smem_u32(const void* p) {
    uint32_t a;
    asm("{ .reg .u64 t; cvta.to.shared.u64 t, %1; cvt.u32.u64 %0, t; }"
        : "=r"(a) : "l"(p));
    return a;
}
__device__ __forceinline__ uint32_t pack_h2(float lo, float hi) {
    __half2 h = __floats2half2_rn(lo, hi);
    return *(uint32_t*)&h;
}
__device__ __forceinline__ void cp16(uint32_t dst, const void* src, int sz) {
    asm volatile("cp.async.cg.shared.global [%0], [%1], 16, %2;"
                 :: "r"(dst), "l"(src), "r"(sz) : "memory");
}
#define CP_COMMIT() asm volatile("cp.async.commit_group;" ::: "memory")
#define CP_WAIT0()  asm volatile("cp.async.wait_group 0;" ::: "memory")

__device__ __forceinline__ void red_v2(float* p, float a, float b) {
    asm volatile("red.global.add.v2.f32 [%0], {%1, %2};"
                 :: "l"(p), "f"(a), "f"(b) : "memory");
}

__device__ __forceinline__ void mma_f16(float& c0, float& c1, float& c2, float& c3,
                                        uint32_t a0, uint32_t a1, uint32_t a2,
                                        uint32_t a3, uint32_t b0, uint32_t b1) {
    asm volatile(
        "mma.sync.aligned.m16n8k16.row.col.f32.f16.f16.f32 "
        "{%0,%1,%2,%3}, {%4,%5,%6,%7}, {%8,%9}, {%0,%1,%2,%3};"
        : "+f"(c0), "+f"(c1), "+f"(c2), "+f"(c3)
        : "r"(a0), "r"(a1), "r"(a2), "r"(a3), "r"(b0), "r"(b1));
}

// ---- prep: fp16 mirror of ref_feat ----------------------------------------
__global__ void ref16_kernel(const float* __restrict__ ref, int nwords) {
    int i = blockIdx.x * blockDim.x + threadIdx.x;
    if (i < nwords) {
        float2 v = ((const float2*)ref)[i];
        g_ref16[i] = pack_h2(v.x, v.y);
    }
}

// ---- sort passes ----------------------------------------------------------
__global__ void init_kernel() {
    if (threadIdx.x < MAXK) g_hist[threadIdx.x] = 0;
}

__global__ void hist_kernel(const int* __restrict__ ek, int E) {
    __shared__ int sh[MAXK];
    if (threadIdx.x < MAXK) sh[threadIdx.x] = 0;
    __syncthreads();
    for (int i = blockIdx.x * blockDim.x + threadIdx.x; i < E;
         i += gridDim.x * blockDim.x)
        atomicAdd(&sh[ek[i]], 1);
    __syncthreads();
    if (threadIdx.x < MAXK) {
        int v = sh[threadIdx.x];
        if (v) atomicAdd(&g_hist[threadIdx.x], v);
    }
}

__global__ void scan_kernel(int K0) {
    if (threadIdx.x == 0 && blockIdx.x == 0) {
        int p = 0, t = 0;
        for (int k = 0; k < K0; ++k) {
            g_pstart[k] = p;
            g_tile_start[k] = t;
            g_cursor[k] = p;
            int c = g_hist[k];
            g_count[k] = c;
            int nt = (c + TILE - 1) / TILE;
            p += nt * TILE;
            t += nt;
        }
        g_pstart[K0] = p;
        g_tile_start[K0] = t;
        g_total_tiles = t;
        for (int k = K0; k < MAXK; ++k) g_tile_start[k + 1] = t;
    }
}

__global__ void scatter_kernel(const int* __restrict__ ek, int E) {
    __shared__ int sc[MAXK], sb[MAXK];
    int chunk = (E + gridDim.x - 1) / gridDim.x;
    int lo = blockIdx.x * chunk;
    int hi = min(lo + chunk, E);
    if (threadIdx.x < MAXK) sc[threadIdx.x] = 0;
    __syncthreads();
    for (int i = lo + threadIdx.x; i < hi; i += blockDim.x)
        atomicAdd(&sc[ek[i]], 1);
    __syncthreads();
    if (threadIdx.x < MAXK) {
        int c = sc[threadIdx.x];
        sb[threadIdx.x] = c ? atomicAdd(&g_cursor[threadIdx.x], c) : 0;
        sc[threadIdx.x] = 0;
    }
    __syncthreads();
    for (int i = lo + threadIdx.x; i < hi; i += blockDim.x) {
        int k = ek[i];
        int pos = sb[k] + atomicAdd(&sc[k], 1);
        g_sorted[pos] = i;
    }
}

// ---- main fused MMA kernel ------------------------------------------------
__global__ __launch_bounds__(256) void mp_mma(
    const float* __restrict__ kernelW,
    const int*   __restrict__ e_ref,
    const int*   __restrict__ e_query,
    const float* __restrict__ e_weight,
    float*       __restrict__ out)
{
    extern __shared__ char sm[];
    uint32_t sa0 = smem_u32(sm + OFF_A0);
    uint32_t sa1 = smem_u32(sm + OFF_A1);
    uint32_t*    s_Bw = (uint32_t*)(sm + OFF_B);
    const uint4* s_B4 = (const uint4*)(sm + OFF_B);
    int   (*s_q)[TILE] = (int (*)[TILE])(sm + OFF_Q);
    float (*s_w)[TILE] = (float (*)[TILE])(sm + OFF_W);
    int* s_mk = (int*)(sm + OFF_MK);
    int* s_mb = (int*)(sm + OFF_MB);
    int* s_mn = (int*)(sm + OFF_MN);
    int* s_ts = (int*)(sm + OFF_TS);
    int* s_ps = (int*)(sm + OFF_PS);
    int* s_cn = (int*)(sm + OFF_CN);

    int tid = threadIdx.x, wid = tid >> 5, lane = tid & 31;
    int g = lane >> 2, t4 = lane & 3;

    if (tid < MAXK + 1) s_ts[tid] = g_tile_start[tid];
    else if (tid >= 64 && tid < 64 + MAXK + 1) s_ps[tid - 64] = g_pstart[tid - 64];
    else if (tid >= 128 && tid < 128 + MAXK) s_cn[tid - 128] = g_count[tid - 128];
    __syncthreads();

    int total = g_total_tiles;
    int per = (total + GRID - 1) / GRID;
    int t0 = blockIdx.x * per;
    int t1 = min(t0 + per, total);
    int ntiles = t1 - t0;
    if (ntiles <= 0) return;

    for (int j = tid; j < ntiles; j += 256) {
        int tile = t0 + j;
        int kk = 0;
        while (tile >= s_ts[kk + 1]) kk++;
        int local = tile - s_ts[kk];
        s_mk[j] = kk;
        s_mb[j] = s_ps[kk] + local * TILE;
        int n = s_cn[kk] - local * TILE;
        s_mn[j] = n > TILE ? TILE : n;
    }
    __syncthreads();

    int row = tid >> 1, half = tid & 1;
    uint32_t dst_off = (uint32_t)row * (SA_WORDS * 4) + (uint32_t)half * 64u;

    // ---- prologue: gather tile 0 ------------------------------------------
    {
        int n0 = s_mn[0], base = s_mb[0];
        int r = -1, q = -1;
        float w = 0.f;
        if (row < n0) {
            int e = g_sorted[base + row];
            r = e_ref[e];
            q = e_query[e];
            w = e_weight[e];
        }
        if (half == 0) { s_q[0][row] = q; s_w[0][row] = w; }
        const char* src =
            (const char*)(g_ref16 + (size_t)(r < 0 ? 0 : r) * 32) + half * 64;
        int sz = (r < 0) ? 0 : 16;
        uint32_t d0 = sa0 + dst_off;
        #pragma unroll
        for (int j = 0; j < 4; ++j) cp16(d0 + j * 16, src + j * 16, sz);
        CP_COMMIT();
    }

    int r_nx = -1, q_nx = -1;
    float w_nx = 0.f;
    if (ntiles > 1) {
        int n1 = s_mn[1], base = s_mb[1];
        if (row < n1) {
            int e = g_sorted[base + row];
            r_nx = e_ref[e];
            q_nx = e_query[e];
            w_nx = e_weight[e];
        }
    }

    int prevk = -1;
    for (int ii = 0; ii < ntiles; ++ii) {
        int buf = ii & 1;
        uint32_t sb_addr = buf ? sa0 : sa1;
        int k = s_mk[ii];

        CP_WAIT0();
        __syncthreads();

        // rebuild fragment-major fp16 B on kernel change (block-uniform)
        if (k != prevk) {
            if (wid < 4) {
                const float* kw = kernelW + (size_t)k * D * D;
                int s = wid;
                uint32_t* bp = s_Bw + (s * 32 + lane) * 20;
                int d0 = s * 16 + 2 * t4;
                #pragma unroll
                for (int n = 0; n < 8; ++n) {
                    int o = 8 * n + g;
                    bp[2 * n]     = pack_h2(kw[d0 * D + o],       kw[(d0 + 1) * D + o]);
                    bp[2 * n + 1] = pack_h2(kw[(d0 + 8) * D + o], kw[(d0 + 9) * D + o]);
                }
            }
            prevk = k;
            __syncthreads();
        }

        // issue gather for tile ii+1
        if (ii + 1 < ntiles) {
            if (half == 0) { s_q[buf ^ 1][row] = q_nx; s_w[buf ^ 1][row] = w_nx; }
            const char* src =
                (const char*)(g_ref16 + (size_t)(r_nx < 0 ? 0 : r_nx) * 32) + half * 64;
            int sz = (r_nx < 0) ? 0 : 16;
            uint32_t d1 = sb_addr + dst_off;
            #pragma unroll
            for (int j = 0; j < 4; ++j) cp16(d1 + j * 16, src + j * 16, sz);
        }
        CP_COMMIT();

        // prefetch indices for tile ii+2
        r_nx = -1; q_nx = -1; w_nx = 0.f;
        if (ii + 2 < ntiles) {
            int nn = s_mn[ii + 2], base = s_mb[ii + 2];
            if (row < nn) {
                int e = g_sorted[base + row];
                r_nx = e_ref[e];
                q_nx = e_query[e];
                w_nx = e_weight[e];
            }
        }

        // ---- MMA: warp owns rows [16w, 16w+16), 4 k16-steps ---------------
        float acc[8][4];
        #pragma unroll
        for (int i = 0; i < 8; ++i)
            #pragma unroll
            for (int j = 0; j < 4; ++j) acc[i][j] = 0.f;

        {
            const uint32_t* A =
                (const uint32_t*)(sm + (buf ? OFF_A1 : OFF_A0));
            const uint32_t* A0 = A + (wid * 16 + g) * SA_WORDS;
            const uint32_t* A1 = A0 + 8 * SA_WORDS;
            #pragma unroll
            for (int s = 0; s < 4; ++s) {
                uint32_t a0 = A0[s * 8 + t4];
                uint32_t a1 = A1[s * 8 + t4];
                uint32_t a2 = A0[s * 8 + t4 + 4];
                uint32_t a3 = A1[s * 8 + t4 + 4];
                const uint4* bp = s_B4 + (s * 160 + lane * 5);
                #pragma unroll
                for (int m = 0; m < 4; ++m) {
                    uint4 bb = bp[m];
                    mma_f16(acc[2 * m][0], acc[2 * m][1], acc[2 * m][2],
                            acc[2 * m][3], a0, a1, a2, a3, bb.x, bb.y);
                    mma_f16(acc[2 * m + 1][0], acc[2 * m + 1][1],
                            acc[2 * m + 1][2], acc[2 * m + 1][3],
                            a0, a1, a2, a3, bb.z, bb.w);
                }
            }
        }

        // ---- epilogue: weight-scale + direct vector atomics ---------------
        {
            int r0 = wid * 16 + g, r1 = r0 + 8;
            int q0 = s_q[buf][r0], q1 = s_q[buf][r1];
            float w0 = s_w[buf][r0], w1 = s_w[buf][r1];
            if (q0 >= 0) {
                float* p0 = out + (size_t)q0 * D + t4 * 2;
                #pragma unroll
                for (int n = 0; n < 8; ++n)
                    red_v2(p0 + n * 8, acc[n][0] * w0, acc[n][1] * w0);
            }
            if (q1 >= 0) {
                float* p1 = out + (size_t)q1 * D + t4 * 2;
                #pragma unroll
                for (int n = 0; n < 8; ++n)
                    red_v2(p1 + n * 8, acc[n][2] * w1, acc[n][3] * w1);
            }
        }
    }
}

// ---------------------------------------------------------------------------
extern "C" void kernel_launch(void* const* d_in, const int* in_sizes, int n_in,
                              void* d_out, int out_size) {
    const float* kernelW  = (const float*)d_in[0];
    const float* ref      = (const float*)d_in[1];
    const int*   e_kernel = (const int*)d_in[2];
    const int*   e_ref    = (const int*)d_in[3];
    const int*   e_query  = (const int*)d_in[4];
    const float* e_weight =
        (n_in >= 7) ? (const float*)d_in[6] : (const float*)d_in[5];

    int E  = in_sizes[2];
    int K0 = in_sizes[0] / (D * D);
    int N  = in_sizes[1] / D;
    int nwords = N * 32;

    cudaMemsetAsync(d_out, 0, (size_t)out_size * sizeof(float), 0);

    ref16_kernel<<<(nwords + 255) / 256, 256>>>(ref, nwords);
    init_kernel<<<1, 32>>>();
    hist_kernel<<<256, 256>>>(e_kernel, E);
    scan_kernel<<<1, 1>>>(K0);
    scatter_kernel<<<592, 256>>>(e_kernel, E);

    cudaFuncSetAttribute(mp_mma, cudaFuncAttributeMaxDynamicSharedMemorySize,
                         DYN_SMEM);
    mp_mma<<<GRID, 256, DYN_SMEM>>>(kernelW, e_ref, e_query, e_weight,
                                    (float*)d_out);
}